// round 3
// baseline (speedup 1.0000x reference)
#include <cuda_runtime.h>
#include <math.h>

#define DM     1024
#define HEADS  16
#define DKH    64
#define BATCH  2
#define SEQ    2048
#define MTOT   (BATCH*SEQ)

// Scratch (static device globals — no allocation inside kernel_launch)
__device__ float g_q[BATCH*HEADS*SEQ*DKH];    // [b][h][s][d]
__device__ float g_k[BATCH*HEADS*SEQ*DKH];
__device__ float g_v[BATCH*HEADS*SEQ*DKH];
__device__ float g_ctx[BATCH*SEQ*DM];         // [b][s][h*64+d]

// ---------------------------------------------------------------------------
// GEMM: C[m][n] = sum_d A[m][d] * W[n][d] + bias[n]
// A: [M][1024] row-major, W: [1024][1024] row-major (both K-contiguous).
// MODE 0: out plain [m][n]   (final projection -> d_out)
// MODE 1: out head layout [b][h][s][d] with h = blockIdx.y (BN == DKH == 64)
// Tiling: BM=BN=64, BK=16, 256 threads, 4x4 microtile per thread.
// ---------------------------------------------------------------------------
template<int MODE>
__global__ __launch_bounds__(256)
void gemm64(const float* __restrict__ A, const float* __restrict__ W,
            const float* __restrict__ bias, float* __restrict__ out)
{
    __shared__ float As[16][68];   // [k][m], padded
    __shared__ float Bs[16][68];   // [k][n], padded

    const int tid = threadIdx.x;
    const int tx  = tid & 15;       // n-direction
    const int ty  = tid >> 4;       // m-direction
    const int m0  = blockIdx.x * 64;
    const int n0  = blockIdx.y * 64;

    const int lr = tid >> 2;        // 0..63 : row of the 64x16 load tile
    const int lc = (tid & 3) * 4;   // 0,4,8,12 : k-col of the float4

    const float* Ap = A + (size_t)(m0 + lr) * DM + lc;
    const float* Wp = W + (size_t)(n0 + lr) * DM + lc;

    float acc[4][4] = {};

    for (int k0 = 0; k0 < DM; k0 += 16) {
        const float4 av = *(const float4*)(Ap + k0);
        const float4 wv = *(const float4*)(Wp + k0);
        __syncthreads();
        As[lc+0][lr] = av.x; As[lc+1][lr] = av.y; As[lc+2][lr] = av.z; As[lc+3][lr] = av.w;
        Bs[lc+0][lr] = wv.x; Bs[lc+1][lr] = wv.y; Bs[lc+2][lr] = wv.z; Bs[lc+3][lr] = wv.w;
        __syncthreads();

        #pragma unroll
        for (int kk = 0; kk < 16; kk++) {
            const float4 a = *(const float4*)&As[kk][ty*4];
            const float4 b = *(const float4*)&Bs[kk][tx*4];
            acc[0][0] += a.x*b.x; acc[0][1] += a.x*b.y; acc[0][2] += a.x*b.z; acc[0][3] += a.x*b.w;
            acc[1][0] += a.y*b.x; acc[1][1] += a.y*b.y; acc[1][2] += a.y*b.z; acc[1][3] += a.y*b.w;
            acc[2][0] += a.z*b.x; acc[2][1] += a.z*b.y; acc[2][2] += a.z*b.z; acc[2][3] += a.z*b.w;
            acc[3][0] += a.w*b.x; acc[3][1] += a.w*b.y; acc[3][2] += a.w*b.z; acc[3][3] += a.w*b.w;
        }
    }

    const float4 bv = *(const float4*)(bias + n0 + tx*4);

    #pragma unroll
    for (int i = 0; i < 4; i++) {
        const int m = m0 + ty*4 + i;
        float4 r;
        r.x = acc[i][0] + bv.x;
        r.y = acc[i][1] + bv.y;
        r.z = acc[i][2] + bv.z;
        r.w = acc[i][3] + bv.w;
        if (MODE == 0) {
            *(float4*)(out + (size_t)m * DM + n0 + tx*4) = r;
        } else {
            const int b = m >> 11;            // /SEQ
            const int s = m & (SEQ - 1);
            const int h = n0 >> 6;            // BN == DKH
            *(float4*)(out + (((size_t)(b*HEADS + h))*SEQ + s)*DKH + tx*4) = r;
        }
    }
}

// ---------------------------------------------------------------------------
// Flash-style attention: one CTA = one (b,h) x 64-row Q block.
// smem: Qt [d][i] 16KB, KV (Kt [d][j] then Vs [k][d]) 16KB, Ps [i][k] 16KB.
// Online softmax, O accumulated in registers (4x4 per thread).
// ---------------------------------------------------------------------------
__global__ __launch_bounds__(256)
void attn_kernel(const int* __restrict__ mask, float* __restrict__ ctx)
{
    __shared__ float Qt[64][64];   // [d][qi]
    __shared__ float KV[64][64];   // phase 1: Kt [d][kj]; phase 2: Vs [k][d]
    __shared__ float Ps[64][64];   // [qi][k]

    const int tid = threadIdx.x;
    const int tx  = tid & 15;
    const int ty  = tid >> 4;
    const int bh  = blockIdx.y;
    const int b   = bh >> 4;
    const int h   = bh & 15;
    const int q0  = blockIdx.x * 64;

    const float* qbase = g_q + (size_t)bh * SEQ * DKH;
    const float* kbase = g_k + (size_t)bh * SEQ * DKH;
    const float* vbase = g_v + (size_t)bh * SEQ * DKH;
    const int*   mbase = mask + (size_t)b * SEQ * SEQ + (size_t)q0 * SEQ;

    // Load Q block transposed: Qt[d][i]
    #pragma unroll
    for (int it = 0; it < 4; it++) {
        const int idx = tid + it * 256;
        const int row = idx >> 4;
        const int c4  = (idx & 15) * 4;
        const float4 v = *(const float4*)(qbase + (size_t)(q0 + row) * DKH + c4);
        Qt[c4+0][row] = v.x; Qt[c4+1][row] = v.y; Qt[c4+2][row] = v.z; Qt[c4+3][row] = v.w;
    }

    float o[4][4] = {};
    float mrow[4] = {-1e30f, -1e30f, -1e30f, -1e30f};
    float lrow[4] = {};

    for (int k0 = 0; k0 < SEQ; k0 += 64) {
        __syncthreads();   // previous iteration done with KV (as Vs) and Ps
        // Load K block transposed: KV[d][j]
        #pragma unroll
        for (int it = 0; it < 4; it++) {
            const int idx = tid + it * 256;
            const int row = idx >> 4;
            const int c4  = (idx & 15) * 4;
            const float4 v = *(const float4*)(kbase + (size_t)(k0 + row) * DKH + c4);
            KV[c4+0][row] = v.x; KV[c4+1][row] = v.y; KV[c4+2][row] = v.z; KV[c4+3][row] = v.w;
        }
        __syncthreads();

        // S = Q K^T (4x4 per thread)
        float s[4][4] = {};
        #pragma unroll 16
        for (int d = 0; d < 64; d++) {
            const float4 a = *(const float4*)&Qt[d][ty*4];
            const float4 c = *(const float4*)&KV[d][tx*4];
            s[0][0] += a.x*c.x; s[0][1] += a.x*c.y; s[0][2] += a.x*c.z; s[0][3] += a.x*c.w;
            s[1][0] += a.y*c.x; s[1][1] += a.y*c.y; s[1][2] += a.y*c.z; s[1][3] += a.y*c.w;
            s[2][0] += a.z*c.x; s[2][1] += a.z*c.y; s[2][2] += a.z*c.z; s[2][3] += a.z*c.w;
            s[3][0] += a.w*c.x; s[3][1] += a.w*c.y; s[3][2] += a.w*c.z; s[3][3] += a.w*c.w;
        }

        // scale + mask
        #pragma unroll
        for (int i = 0; i < 4; i++) {
            #pragma unroll
            for (int j = 0; j < 4; j++) {
                const float sv = s[i][j] * 0.125f;   // 1/sqrt(64)
                const int mv = mbase[(size_t)(ty*4 + i) * SEQ + k0 + tx*4 + j];
                s[i][j] = (mv == 0) ? -1e9f : sv;
            }
        }

        // online softmax per row; row group = 16 lanes sharing ty (width-16 shuffles)
        #pragma unroll
        for (int r = 0; r < 4; r++) {
            float mx = fmaxf(fmaxf(s[r][0], s[r][1]), fmaxf(s[r][2], s[r][3]));
            #pragma unroll
            for (int t = 8; t > 0; t >>= 1)
                mx = fmaxf(mx, __shfl_xor_sync(0xffffffffu, mx, t, 16));
            const float nm   = fmaxf(mrow[r], mx);
            const float corr = __expf(mrow[r] - nm);
            mrow[r] = nm;

            const float p0 = __expf(s[r][0] - nm);
            const float p1 = __expf(s[r][1] - nm);
            const float p2 = __expf(s[r][2] - nm);
            const float p3 = __expf(s[r][3] - nm);
            float rs = p0 + p1 + p2 + p3;
            #pragma unroll
            for (int t = 8; t > 0; t >>= 1)
                rs += __shfl_xor_sync(0xffffffffu, rs, t, 16);
            lrow[r] = lrow[r] * corr + rs;

            o[r][0] *= corr; o[r][1] *= corr; o[r][2] *= corr; o[r][3] *= corr;

            Ps[ty*4 + r][tx*4 + 0] = p0;
            Ps[ty*4 + r][tx*4 + 1] = p1;
            Ps[ty*4 + r][tx*4 + 2] = p2;
            Ps[ty*4 + r][tx*4 + 3] = p3;
        }
        __syncthreads();   // Kt reads & Ps writes complete

        // Load V block natural: KV[k][d]  (reuses Kt buffer)
        #pragma unroll
        for (int it = 0; it < 4; it++) {
            const int idx = tid + it * 256;
            const int row = idx >> 4;
            const int c4  = (idx & 15) * 4;
            *(float4*)&KV[row][c4] = *(const float4*)(vbase + (size_t)(k0 + row) * DKH + c4);
        }
        __syncthreads();

        // O += P V
        #pragma unroll 8
        for (int k = 0; k < 64; k++) {
            const float4 vv = *(const float4*)&KV[k][tx*4];
            #pragma unroll
            for (int i = 0; i < 4; i++) {
                const float p = Ps[ty*4 + i][k];
                o[i][0] += p * vv.x; o[i][1] += p * vv.y;
                o[i][2] += p * vv.z; o[i][3] += p * vv.w;
            }
        }
    }

    // Normalize and write ctx in [b][s][h*64+d] layout
    #pragma unroll
    for (int i = 0; i < 4; i++) {
        const float inv = 1.0f / lrow[i];
        float4 r;
        r.x = o[i][0] * inv; r.y = o[i][1] * inv;
        r.z = o[i][2] * inv; r.w = o[i][3] * inv;
        const int s = q0 + ty*4 + i;
        *(float4*)(g_ctx + ((size_t)(b*SEQ) + s) * DM + h*DKH + tx*4) = r;
    }
}

// ---------------------------------------------------------------------------
extern "C" void kernel_launch(void* const* d_in, const int* in_sizes, int n_in,
                              void* d_out, int out_size)
{
    (void)in_sizes; (void)n_in; (void)out_size;
    const float* hid  = (const float*)d_in[0];
    const int*   mask = (const int*)  d_in[1];
    const float* Wq   = (const float*)d_in[2];
    const float* bq   = (const float*)d_in[3];
    const float* Wk   = (const float*)d_in[4];
    const float* bk   = (const float*)d_in[5];
    const float* Wv   = (const float*)d_in[6];
    const float* bv   = (const float*)d_in[7];
    const float* Wo   = (const float*)d_in[8];
    const float* bo   = (const float*)d_in[9];
    float* out = (float*)d_out;

    float *qp, *kp, *vp, *cp;
    cudaGetSymbolAddress((void**)&qp, g_q);
    cudaGetSymbolAddress((void**)&kp, g_k);
    cudaGetSymbolAddress((void**)&vp, g_v);
    cudaGetSymbolAddress((void**)&cp, g_ctx);

    const dim3 gproj(MTOT/64, DM/64);       // 64 x 16
    gemm64<1><<<gproj, 256>>>(hid, Wq, bq, qp);
    gemm64<1><<<gproj, 256>>>(hid, Wk, bk, kp);
    gemm64<1><<<gproj, 256>>>(hid, Wv, bv, vp);

    attn_kernel<<<dim3(SEQ/64, BATCH*HEADS), 256>>>(mask, cp);

    gemm64<0><<<gproj, 256>>>(cp, Wo, bo, out);
}

// round 5
// speedup vs baseline: 1.3629x; 1.3629x over previous
#include <cuda_runtime.h>
#include <cuda_bf16.h>
#include <stdint.h>
#include <math.h>

#define DM     1024
#define HEADS  16
#define DKH    64
#define BATCH  2
#define SEQ    2048
#define MTOT   (BATCH*SEQ)
#define GK     3072            // split-bf16 concatenated K

// ---------------- scratch (static device globals) --------------------------
__device__ uint4 g_abig[(size_t)MTOT * GK * 2 / 16];      // bf16 [4096][3072]
__device__ uint4 g_wbig[(size_t)4 * DM * GK * 2 / 16];    // 4 x bf16 [1024][3072]
__device__ uint4 g_cbig[(size_t)MTOT * GK * 2 / 16];      // bf16 [4096][3072]
__device__ float g_q[(size_t)MTOT * DM];                  // plain [m][1024]
__device__ float g_k[(size_t)MTOT * DM];
__device__ float g_v[(size_t)MTOT * DM];
__device__ float g_ctx[(size_t)MTOT * DM];

// ---------------- small helpers --------------------------------------------
__device__ __forceinline__ uint32_t smem_u32(const void* p) {
    uint32_t a;
    asm("{ .reg .u64 t; cvta.to.shared.u64 t, %1; cvt.u32.u64 %0, t; }" : "=r"(a) : "l"(p));
    return a;
}
__device__ __forceinline__ void cpa16(uint32_t s, const void* g) {
    asm volatile("cp.async.cg.shared.global [%0], [%1], 16;" :: "r"(s), "l"(g));
}
#define CPA_COMMIT() asm volatile("cp.async.commit_group;" ::: "memory")
#define CPA_WAIT(N)  asm volatile("cp.async.wait_group %0;" :: "n"(N) : "memory")

__device__ __forceinline__ void ldsm4(uint32_t& r0, uint32_t& r1, uint32_t& r2, uint32_t& r3,
                                      uint32_t addr) {
    asm volatile("ldmatrix.sync.aligned.m8n8.x4.shared.b16 {%0,%1,%2,%3}, [%4];"
                 : "=r"(r0), "=r"(r1), "=r"(r2), "=r"(r3) : "r"(addr));
}
__device__ __forceinline__ void mma16816(float& d0, float& d1, float& d2, float& d3,
                                         uint32_t a0, uint32_t a1, uint32_t a2, uint32_t a3,
                                         uint32_t b0, uint32_t b1) {
    asm volatile("mma.sync.aligned.m16n8k16.row.col.f32.bf16.bf16.f32 "
                 "{%0,%1,%2,%3}, {%4,%5,%6,%7}, {%8,%9}, {%0,%1,%2,%3};"
                 : "+f"(d0), "+f"(d1), "+f"(d2), "+f"(d3)
                 : "r"(a0), "r"(a1), "r"(a2), "r"(a3), "r"(b0), "r"(b1));
}

// ---------------------------------------------------------------------------
// split: X fp32 [rows][1024] -> Y bf16 [rows][3072]
// SIDE 0 (A operand): segments (hi, hi, lo);  SIDE 1 (B): (hi, lo, hi)
// ---------------------------------------------------------------------------
template<int SIDE>
__global__ __launch_bounds__(256)
void split_kernel(const float* __restrict__ X, __nv_bfloat16* __restrict__ Y)
{
    const int idx = blockIdx.x * 256 + threadIdx.x;
    const int r   = idx >> 8;
    const int c4  = (idx & 255) * 4;
    const float4 x = *(const float4*)(X + (size_t)r * DM + c4);

    __nv_bfloat16 h0 = __float2bfloat16(x.x), h1 = __float2bfloat16(x.y);
    __nv_bfloat16 h2 = __float2bfloat16(x.z), h3 = __float2bfloat16(x.w);
    __nv_bfloat16 l0 = __float2bfloat16(x.x - __bfloat162float(h0));
    __nv_bfloat16 l1 = __float2bfloat16(x.y - __bfloat162float(h1));
    __nv_bfloat16 l2 = __float2bfloat16(x.z - __bfloat162float(h2));
    __nv_bfloat16 l3 = __float2bfloat16(x.w - __bfloat162float(h3));

    __nv_bfloat162 hA = __halves2bfloat162(h0,h1), hB = __halves2bfloat162(h2,h3);
    __nv_bfloat162 lA = __halves2bfloat162(l0,l1), lB = __halves2bfloat162(l2,l3);

    __nv_bfloat162* y0 = (__nv_bfloat162*)(Y + (size_t)r * GK + c4);
    __nv_bfloat162* y1 = (__nv_bfloat162*)(Y + (size_t)r * GK + 1024 + c4);
    __nv_bfloat162* y2 = (__nv_bfloat162*)(Y + (size_t)r * GK + 2048 + c4);
    y0[0] = hA; y0[1] = hB;
    if (SIDE == 0) { y1[0] = hA; y1[1] = hB; y2[0] = lA; y2[1] = lB; }
    else           { y1[0] = lA; y1[1] = lB; y2[0] = hA; y2[1] = hB; }
}

// ---------------------------------------------------------------------------
// HMMA GEMM: out[m][n] = sum_k A[m][k]*B[n][k] + bias[n]
// A bf16 [MTOT][3072], B bf16 [1024][3072], out fp32 [MTOT][1024]
// Tile 128x128, BK=32, 256 threads (8 warps, 2x4), warp tile 64x32,
// cp.async double-buffered, padded 80B smem rows (ldmatrix conflict-free).
// ---------------------------------------------------------------------------
#define ROWB   80
#define TILEB  (128*ROWB)              // 10240 bytes per operand tile
#define HS_A0  0
#define HS_B0  TILEB
#define HS_A1  (2*TILEB)
#define HS_B1  (3*TILEB)
#define HSMEM  (4*TILEB)               // 40960

__global__ __launch_bounds__(256, 2)
void hgemm(const __nv_bfloat16* __restrict__ A, const __nv_bfloat16* __restrict__ B,
           const float* __restrict__ bias, float* __restrict__ out)
{
    extern __shared__ char sm[];
    const uint32_t sbase = smem_u32(sm);
    const int tid  = threadIdx.x;
    const int m0   = blockIdx.x * 128;
    const int n0   = blockIdx.y * 128;

    // load mapping: 512 16B-chunks per operand tile; thread handles chunks tid, tid+256
    const int r0c = tid >> 2,  c0c = tid & 3;        // rows 0..63
    const int r1c = r0c + 64;                        // rows 64..127
    const __nv_bfloat16* Ag0 = A + (size_t)(m0 + r0c) * GK + c0c * 8;
    const __nv_bfloat16* Ag1 = A + (size_t)(m0 + r1c) * GK + c0c * 8;
    const __nv_bfloat16* Bg0 = B + (size_t)(n0 + r0c) * GK + c0c * 8;
    const __nv_bfloat16* Bg1 = B + (size_t)(n0 + r1c) * GK + c0c * 8;
    const uint32_t sA_off0 = r0c * ROWB + c0c * 16;
    const uint32_t sA_off1 = r1c * ROWB + c0c * 16;

    const uint32_t abuf[2] = { sbase + HS_A0, sbase + HS_A1 };
    const uint32_t bbuf[2] = { sbase + HS_B0, sbase + HS_B1 };

    const int wid  = tid >> 5, lane = tid & 31;
    const int wm   = (wid >> 2) * 64;      // 0 / 64
    const int wn   = (wid & 3) * 32;       // 0..96

    // per-lane fragment smem offsets (within a tile buffer)
    const uint32_t aoff = (uint32_t)(wm + (lane & 15)) * ROWB + (lane >> 4) * 16;
    const uint32_t boff = (uint32_t)(wn + ((lane >> 4) & 1) * 8 + (lane & 7)) * ROWB
                        + ((lane >> 3) & 1) * 16;

    float acc[4][4][4] = {};

    #define LOAD_TILE(it, buf) do {                                            \
        const size_t kb = (size_t)(it) * 32;                                   \
        cpa16(abuf[buf] + sA_off0, Ag0 + kb);                                  \
        cpa16(abuf[buf] + sA_off1, Ag1 + kb);                                  \
        cpa16(bbuf[buf] + sA_off0, Bg0 + kb);                                  \
        cpa16(bbuf[buf] + sA_off1, Bg1 + kb);                                  \
        CPA_COMMIT();                                                          \
    } while (0)

    LOAD_TILE(0, 0);

    const int KITERS = GK / 32;   // 96
    for (int it = 0; it < KITERS; it++) {
        const int cur = it & 1;
        if (it + 1 < KITERS) { LOAD_TILE(it + 1, cur ^ 1); CPA_WAIT(1); }
        else                 { CPA_WAIT(0); }
        __syncthreads();

        #pragma unroll
        for (int kk = 0; kk < 2; kk++) {            // two k16 steps
            const uint32_t kb = kk * 32;            // byte offset of k16
            uint32_t a[4][4], b[4][2];
            #pragma unroll
            for (int mt = 0; mt < 4; mt++)
                ldsm4(a[mt][0], a[mt][1], a[mt][2], a[mt][3],
                      abuf[cur] + aoff + (uint32_t)mt * (16*ROWB) + kb);
            #pragma unroll
            for (int np = 0; np < 2; np++) {
                uint32_t q0,q1,q2,q3;
                ldsm4(q0,q1,q2,q3, bbuf[cur] + boff + (uint32_t)np * (16*ROWB) + kb);
                b[np*2+0][0] = q0; b[np*2+0][1] = q1;
                b[np*2+1][0] = q2; b[np*2+1][1] = q3;
            }
            #pragma unroll
            for (int mt = 0; mt < 4; mt++)
                #pragma unroll
                for (int nt = 0; nt < 4; nt++)
                    mma16816(acc[mt][nt][0], acc[mt][nt][1], acc[mt][nt][2], acc[mt][nt][3],
                             a[mt][0], a[mt][1], a[mt][2], a[mt][3],
                             b[nt][0], b[nt][1]);
        }
        __syncthreads();
    }

    // epilogue: d0,d1 -> row lane/4, cols (lane%4)*2 ; d2,d3 -> row+8
    const int erow = lane >> 2;
    const int ecol = (lane & 3) * 2;
    #pragma unroll
    for (int nt = 0; nt < 4; nt++) {
        const int col = n0 + wn + nt * 8 + ecol;
        const float2 bv = *(const float2*)(bias + col);
        #pragma unroll
        for (int mt = 0; mt < 4; mt++) {
            const int m = m0 + wm + mt * 16 + erow;
            float2 w0, w1;
            w0.x = acc[mt][nt][0] + bv.x; w0.y = acc[mt][nt][1] + bv.y;
            w1.x = acc[mt][nt][2] + bv.x; w1.y = acc[mt][nt][3] + bv.y;
            *(float2*)(out + (size_t)m * DM + col)       = w0;
            *(float2*)(out + (size_t)(m + 8) * DM + col) = w1;
        }
    }
    #undef LOAD_TILE
}

// ---------------------------------------------------------------------------
// Flash-style fp32 attention; q/k/v plain [m][1024], head h = cols h*64..+63
// ---------------------------------------------------------------------------
__global__ __launch_bounds__(256)
void attn_kernel(const int* __restrict__ mask, float* __restrict__ ctx)
{
    __shared__ float Qt[64][64];
    __shared__ float KV[64][64];
    __shared__ float Ps[64][64];

    const int tid = threadIdx.x;
    const int tx  = tid & 15;
    const int ty  = tid >> 4;
    const int bh  = blockIdx.y;
    const int b   = bh >> 4;
    const int h   = bh & 15;
    const int q0  = blockIdx.x * 64;

    const float* qbase = g_q + (size_t)b * SEQ * DM + (size_t)h * DKH;
    const float* kbase = g_k + (size_t)b * SEQ * DM + (size_t)h * DKH;
    const float* vbase = g_v + (size_t)b * SEQ * DM + (size_t)h * DKH;
    const int*   mbase = mask + (size_t)b * SEQ * SEQ + (size_t)q0 * SEQ;

    #pragma unroll
    for (int it = 0; it < 4; it++) {
        const int idx = tid + it * 256;
        const int row = idx >> 4;
        const int c4  = (idx & 15) * 4;
        const float4 v = *(const float4*)(qbase + (size_t)(q0 + row) * DM + c4);
        Qt[c4+0][row] = v.x; Qt[c4+1][row] = v.y; Qt[c4+2][row] = v.z; Qt[c4+3][row] = v.w;
    }

    float o[4][4] = {};
    float mrow[4] = {-1e30f, -1e30f, -1e30f, -1e30f};
    float lrow[4] = {};

    for (int k0 = 0; k0 < SEQ; k0 += 64) {
        __syncthreads();
        #pragma unroll
        for (int it = 0; it < 4; it++) {
            const int idx = tid + it * 256;
            const int row = idx >> 4;
            const int c4  = (idx & 15) * 4;
            const float4 v = *(const float4*)(kbase + (size_t)(k0 + row) * DM + c4);
            KV[c4+0][row] = v.x; KV[c4+1][row] = v.y; KV[c4+2][row] = v.z; KV[c4+3][row] = v.w;
        }
        __syncthreads();

        float s[4][4] = {};
        #pragma unroll 16
        for (int d = 0; d < 64; d++) {
            const float4 a = *(const float4*)&Qt[d][ty*4];
            const float4 c = *(const float4*)&KV[d][tx*4];
            s[0][0] += a.x*c.x; s[0][1] += a.x*c.y; s[0][2] += a.x*c.z; s[0][3] += a.x*c.w;
            s[1][0] += a.y*c.x; s[1][1] += a.y*c.y; s[1][2] += a.y*c.z; s[1][3] += a.y*c.w;
            s[2][0] += a.z*c.x; s[2][1] += a.z*c.y; s[2][2] += a.z*c.z; s[2][3] += a.z*c.w;
            s[3][0] += a.w*c.x; s[3][1] += a.w*c.y; s[3][2] += a.w*c.z; s[3][3] += a.w*c.w;
        }

        #pragma unroll
        for (int i = 0; i < 4; i++) {
            const int4 mv = *(const int4*)(mbase + (size_t)(ty*4 + i) * SEQ + k0 + tx*4);
            s[i][0] = (mv.x == 0) ? -1e9f : s[i][0] * 0.125f;
            s[i][1] = (mv.y == 0) ? -1e9f : s[i][1] * 0.125f;
            s[i][2] = (mv.z == 0) ? -1e9f : s[i][2] * 0.125f;
            s[i][3] = (mv.w == 0) ? -1e9f : s[i][3] * 0.125f;
        }

        #pragma unroll
        for (int r = 0; r < 4; r++) {
            float mx = fmaxf(fmaxf(s[r][0], s[r][1]), fmaxf(s[r][2], s[r][3]));
            #pragma unroll
            for (int t = 8; t > 0; t >>= 1)
                mx = fmaxf(mx, __shfl_xor_sync(0xffffffffu, mx, t, 16));
            const float nm   = fmaxf(mrow[r], mx);
            const float corr = __expf(mrow[r] - nm);
            mrow[r] = nm;

            const float p0 = __expf(s[r][0] - nm);
            const float p1 = __expf(s[r][1] - nm);
            const float p2 = __expf(s[r][2] - nm);
            const float p3 = __expf(s[r][3] - nm);
            float rs = p0 + p1 + p2 + p3;
            #pragma unroll
            for (int t = 8; t > 0; t >>= 1)
                rs += __shfl_xor_sync(0xffffffffu, rs, t, 16);
            lrow[r] = lrow[r] * corr + rs;

            o[r][0] *= corr; o[r][1] *= corr; o[r][2] *= corr; o[r][3] *= corr;

            Ps[ty*4 + r][tx*4 + 0] = p0;
            Ps[ty*4 + r][tx*4 + 1] = p1;
            Ps[ty*4 + r][tx*4 + 2] = p2;
            Ps[ty*4 + r][tx*4 + 3] = p3;
        }
        __syncthreads();

        #pragma unroll
        for (int it = 0; it < 4; it++) {
            const int idx = tid + it * 256;
            const int row = idx >> 4;
            const int c4  = (idx & 15) * 4;
            *(float4*)&KV[row][c4] = *(const float4*)(vbase + (size_t)(k0 + row) * DM + c4);
        }
        __syncthreads();

        #pragma unroll 4
        for (int k = 0; k < 64; k += 4) {
            const float4 v0 = *(const float4*)&KV[k+0][tx*4];
            const float4 v1 = *(const float4*)&KV[k+1][tx*4];
            const float4 v2 = *(const float4*)&KV[k+2][tx*4];
            const float4 v3 = *(const float4*)&KV[k+3][tx*4];
            #pragma unroll
            for (int i = 0; i < 4; i++) {
                const float4 pp = *(const float4*)&Ps[ty*4 + i][k];
                o[i][0] += pp.x*v0.x + pp.y*v1.x + pp.z*v2.x + pp.w*v3.x;
                o[i][1] += pp.x*v0.y + pp.y*v1.y + pp.z*v2.y + pp.w*v3.y;
                o[i][2] += pp.x*v0.z + pp.y*v1.z + pp.z*v2.z + pp.w*v3.z;
                o[i][3] += pp.x*v0.w + pp.y*v1.w + pp.z*v2.w + pp.w*v3.w;
            }
        }
    }

    #pragma unroll
    for (int i = 0; i < 4; i++) {
        const float inv = 1.0f / lrow[i];
        float4 r;
        r.x = o[i][0] * inv; r.y = o[i][1] * inv;
        r.z = o[i][2] * inv; r.w = o[i][3] * inv;
        const int s = q0 + ty*4 + i;
        *(float4*)(g_ctx + ((size_t)(b*SEQ) + s) * DM + h*DKH + tx*4) = r;
    }
}

// ---------------------------------------------------------------------------
extern "C" void kernel_launch(void* const* d_in, const int* in_sizes, int n_in,
                              void* d_out, int out_size)
{
    (void)in_sizes; (void)n_in; (void)out_size;
    const float* hid  = (const float*)d_in[0];
    const int*   mask = (const int*)  d_in[1];
    const float* Wq   = (const float*)d_in[2];
    const float* bq   = (const float*)d_in[3];
    const float* Wk   = (const float*)d_in[4];
    const float* bk   = (const float*)d_in[5];
    const float* Wv   = (const float*)d_in[6];
    const float* bv   = (const float*)d_in[7];
    const float* Wo   = (const float*)d_in[8];
    const float* bo   = (const float*)d_in[9];
    float* out = (float*)d_out;

    uint4 *ab, *wb, *cb;
    float *qp, *kp, *vp, *cp;
    cudaGetSymbolAddress((void**)&ab, g_abig);
    cudaGetSymbolAddress((void**)&wb, g_wbig);
    cudaGetSymbolAddress((void**)&cb, g_cbig);
    cudaGetSymbolAddress((void**)&qp, g_q);
    cudaGetSymbolAddress((void**)&kp, g_k);
    cudaGetSymbolAddress((void**)&vp, g_v);
    cudaGetSymbolAddress((void**)&cp, g_ctx);

    const size_t WOFF = (size_t)DM * GK / 8;   // uint4 per split weight matrix

    split_kernel<0><<<MTOT, 256>>>(hid, (__nv_bfloat16*)ab);
    split_kernel<1><<<DM, 256>>>(Wq, (__nv_bfloat16*)(wb + 0*WOFF));
    split_kernel<1><<<DM, 256>>>(Wk, (__nv_bfloat16*)(wb + 1*WOFF));
    split_kernel<1><<<DM, 256>>>(Wv, (__nv_bfloat16*)(wb + 2*WOFF));
    split_kernel<1><<<DM, 256>>>(Wo, (__nv_bfloat16*)(wb + 3*WOFF));

    const dim3 gg(MTOT/128, DM/128);           // 32 x 8
    hgemm<<<gg, 256, HSMEM>>>((const __nv_bfloat16*)ab, (const __nv_bfloat16*)(wb + 0*WOFF), bq, qp);
    hgemm<<<gg, 256, HSMEM>>>((const __nv_bfloat16*)ab, (const __nv_bfloat16*)(wb + 1*WOFF), bk, kp);
    hgemm<<<gg, 256, HSMEM>>>((const __nv_bfloat16*)ab, (const __nv_bfloat16*)(wb + 2*WOFF), bv, vp);

    attn_kernel<<<dim3(SEQ/64, BATCH*HEADS), 256>>>(mask, cp);

    split_kernel<0><<<MTOT, 256>>>(cp, (__nv_bfloat16*)cb);
    hgemm<<<gg, 256, HSMEM>>>((const __nv_bfloat16*)cb, (const __nv_bfloat16*)(wb + 3*WOFF), bo, out);
}

// round 6
// speedup vs baseline: 1.9746x; 1.4488x over previous
#include <cuda_runtime.h>
#include <cuda_bf16.h>
#include <stdint.h>
#include <math.h>

#define DM     1024
#define HEADS  16
#define DKH    64
#define BATCH  2
#define SEQ    2048
#define MTOT   (BATCH*SEQ)
#define GK     3072            // split-bf16 concatenated K (projections)

// ---------------- scratch (static device globals) --------------------------
__device__ uint4 g_abig[(size_t)MTOT * GK * 2 / 16];      // bf16 [4096][3072]
__device__ uint4 g_wbig[(size_t)4 * DM * GK * 2 / 16];    // 4 x bf16 [1024][3072]
__device__ uint4 g_cbig[(size_t)MTOT * GK * 2 / 16];      // bf16 [4096][3072]
__device__ float g_q[(size_t)MTOT * DM];                  // fp32 [m][1024]
__device__ float g_k[(size_t)MTOT * DM];
__device__ float g_v[(size_t)MTOT * DM];
__device__ float g_ctx[(size_t)MTOT * DM];
// attention operands
__device__ uint4 g_qs[(size_t)32 * SEQ * 192 * 2 / 16];   // bf16 [bh][s][192] (hi,hi,lo)
__device__ uint4 g_ks[(size_t)32 * SEQ * 192 * 2 / 16];   // bf16 [bh][s][192] (hi,lo,hi)
__device__ uint4 g_vt[(size_t)32 * 2 * DKH * SEQ * 2 / 16]; // bf16 [bh][seg][d][s]

// ---------------- small helpers --------------------------------------------
__device__ __forceinline__ uint32_t smem_u32(const void* p) {
    uint32_t a;
    asm("{ .reg .u64 t; cvta.to.shared.u64 t, %1; cvt.u32.u64 %0, t; }" : "=r"(a) : "l"(p));
    return a;
}
__device__ __forceinline__ void cpa16(uint32_t s, const void* g) {
    asm volatile("cp.async.cg.shared.global [%0], [%1], 16;" :: "r"(s), "l"(g));
}
#define CPA_COMMIT() asm volatile("cp.async.commit_group;" ::: "memory")
#define CPA_WAIT(N)  asm volatile("cp.async.wait_group %0;" :: "n"(N) : "memory")

__device__ __forceinline__ void ldsm4(uint32_t& r0, uint32_t& r1, uint32_t& r2, uint32_t& r3,
                                      uint32_t addr) {
    asm volatile("ldmatrix.sync.aligned.m8n8.x4.shared.b16 {%0,%1,%2,%3}, [%4];"
                 : "=r"(r0), "=r"(r1), "=r"(r2), "=r"(r3) : "r"(addr));
}
__device__ __forceinline__ void mma16816(float& d0, float& d1, float& d2, float& d3,
                                         uint32_t a0, uint32_t a1, uint32_t a2, uint32_t a3,
                                         uint32_t b0, uint32_t b1) {
    asm volatile("mma.sync.aligned.m16n8k16.row.col.f32.bf16.bf16.f32 "
                 "{%0,%1,%2,%3}, {%4,%5,%6,%7}, {%8,%9}, {%0,%1,%2,%3};"
                 : "+f"(d0), "+f"(d1), "+f"(d2), "+f"(d3)
                 : "r"(a0), "r"(a1), "r"(a2), "r"(a3), "r"(b0), "r"(b1));
}
__device__ __forceinline__ uint32_t packbf2(float lo, float hi) {
    __nv_bfloat162 t = __floats2bfloat162_rn(lo, hi);
    return *(uint32_t*)&t;
}

// ---------------------------------------------------------------------------
// split: X fp32 [rows][1024] -> Y bf16 [rows][3072]
// SIDE 0 (A operand): (hi,hi,lo);  SIDE 1 (B): (hi,lo,hi)
// ---------------------------------------------------------------------------
template<int SIDE>
__global__ __launch_bounds__(256)
void split_kernel(const float* __restrict__ X, __nv_bfloat16* __restrict__ Y)
{
    const int idx = blockIdx.x * 256 + threadIdx.x;
    const int r   = idx >> 8;
    const int c4  = (idx & 255) * 4;
    const float4 x = *(const float4*)(X + (size_t)r * DM + c4);

    __nv_bfloat16 h0 = __float2bfloat16(x.x), h1 = __float2bfloat16(x.y);
    __nv_bfloat16 h2 = __float2bfloat16(x.z), h3 = __float2bfloat16(x.w);
    __nv_bfloat16 l0 = __float2bfloat16(x.x - __bfloat162float(h0));
    __nv_bfloat16 l1 = __float2bfloat16(x.y - __bfloat162float(h1));
    __nv_bfloat16 l2 = __float2bfloat16(x.z - __bfloat162float(h2));
    __nv_bfloat16 l3 = __float2bfloat16(x.w - __bfloat162float(h3));

    __nv_bfloat162 hA = __halves2bfloat162(h0,h1), hB = __halves2bfloat162(h2,h3);
    __nv_bfloat162 lA = __halves2bfloat162(l0,l1), lB = __halves2bfloat162(l2,l3);

    __nv_bfloat162* y0 = (__nv_bfloat162*)(Y + (size_t)r * GK + c4);
    __nv_bfloat162* y1 = (__nv_bfloat162*)(Y + (size_t)r * GK + 1024 + c4);
    __nv_bfloat162* y2 = (__nv_bfloat162*)(Y + (size_t)r * GK + 2048 + c4);
    y0[0] = hA; y0[1] = hB;
    if (SIDE == 0) { y1[0] = hA; y1[1] = hB; y2[0] = lA; y2[1] = lB; }
    else           { y1[0] = lA; y1[1] = lB; y2[0] = hA; y2[1] = hB; }
}

// ---------------------------------------------------------------------------
// HMMA GEMM (unchanged from R4 — known good)
// ---------------------------------------------------------------------------
#define ROWB   80
#define TILEB  (128*ROWB)
#define HS_A0  0
#define HS_B0  TILEB
#define HS_A1  (2*TILEB)
#define HS_B1  (3*TILEB)
#define HSMEM  (4*TILEB)

__global__ __launch_bounds__(256, 2)
void hgemm(const __nv_bfloat16* __restrict__ A, const __nv_bfloat16* __restrict__ B,
           const float* __restrict__ bias, float* __restrict__ out)
{
    extern __shared__ char sm[];
    const uint32_t sbase = smem_u32(sm);
    const int tid  = threadIdx.x;
    const int m0   = blockIdx.x * 128;
    const int n0   = blockIdx.y * 128;

    const int r0c = tid >> 2,  c0c = tid & 3;
    const int r1c = r0c + 64;
    const __nv_bfloat16* Ag0 = A + (size_t)(m0 + r0c) * GK + c0c * 8;
    const __nv_bfloat16* Ag1 = A + (size_t)(m0 + r1c) * GK + c0c * 8;
    const __nv_bfloat16* Bg0 = B + (size_t)(n0 + r0c) * GK + c0c * 8;
    const __nv_bfloat16* Bg1 = B + (size_t)(n0 + r1c) * GK + c0c * 8;
    const uint32_t sA_off0 = r0c * ROWB + c0c * 16;
    const uint32_t sA_off1 = r1c * ROWB + c0c * 16;

    const uint32_t abuf[2] = { sbase + HS_A0, sbase + HS_A1 };
    const uint32_t bbuf[2] = { sbase + HS_B0, sbase + HS_B1 };

    const int wid  = tid >> 5, lane = tid & 31;
    const int wm   = (wid >> 2) * 64;
    const int wn   = (wid & 3) * 32;

    const uint32_t aoff = (uint32_t)(wm + (lane & 15)) * ROWB + (lane >> 4) * 16;
    const uint32_t boff = (uint32_t)(wn + ((lane >> 4) & 1) * 8 + (lane & 7)) * ROWB
                        + ((lane >> 3) & 1) * 16;

    float acc[4][4][4] = {};

    #define LOAD_TILE(it, buf) do {                                            \
        const size_t kb = (size_t)(it) * 32;                                   \
        cpa16(abuf[buf] + sA_off0, Ag0 + kb);                                  \
        cpa16(abuf[buf] + sA_off1, Ag1 + kb);                                  \
        cpa16(bbuf[buf] + sA_off0, Bg0 + kb);                                  \
        cpa16(bbuf[buf] + sA_off1, Bg1 + kb);                                  \
        CPA_COMMIT();                                                          \
    } while (0)

    LOAD_TILE(0, 0);

    const int KITERS = GK / 32;
    for (int it = 0; it < KITERS; it++) {
        const int cur = it & 1;
        if (it + 1 < KITERS) { LOAD_TILE(it + 1, cur ^ 1); CPA_WAIT(1); }
        else                 { CPA_WAIT(0); }
        __syncthreads();

        #pragma unroll
        for (int kk = 0; kk < 2; kk++) {
            const uint32_t kb = kk * 32;
            uint32_t a[4][4], b[4][2];
            #pragma unroll
            for (int mt = 0; mt < 4; mt++)
                ldsm4(a[mt][0], a[mt][1], a[mt][2], a[mt][3],
                      abuf[cur] + aoff + (uint32_t)mt * (16*ROWB) + kb);
            #pragma unroll
            for (int np = 0; np < 2; np++) {
                uint32_t q0,q1,q2,q3;
                ldsm4(q0,q1,q2,q3, bbuf[cur] + boff + (uint32_t)np * (16*ROWB) + kb);
                b[np*2+0][0] = q0; b[np*2+0][1] = q1;
                b[np*2+1][0] = q2; b[np*2+1][1] = q3;
            }
            #pragma unroll
            for (int mt = 0; mt < 4; mt++)
                #pragma unroll
                for (int nt = 0; nt < 4; nt++)
                    mma16816(acc[mt][nt][0], acc[mt][nt][1], acc[mt][nt][2], acc[mt][nt][3],
                             a[mt][0], a[mt][1], a[mt][2], a[mt][3],
                             b[nt][0], b[nt][1]);
        }
        __syncthreads();
    }

    const int erow = lane >> 2;
    const int ecol = (lane & 3) * 2;
    #pragma unroll
    for (int nt = 0; nt < 4; nt++) {
        const int col = n0 + wn + nt * 8 + ecol;
        const float2 bv = *(const float2*)(bias + col);
        #pragma unroll
        for (int mt = 0; mt < 4; mt++) {
            const int m = m0 + wm + mt * 16 + erow;
            float2 w0, w1;
            w0.x = acc[mt][nt][0] + bv.x; w0.y = acc[mt][nt][1] + bv.y;
            w1.x = acc[mt][nt][2] + bv.x; w1.y = acc[mt][nt][3] + bv.y;
            *(float2*)(out + (size_t)m * DM + col)       = w0;
            *(float2*)(out + (size_t)(m + 8) * DM + col) = w1;
        }
    }
    #undef LOAD_TILE
}

// ---------------------------------------------------------------------------
// qk_split: fp32 [m][1024] -> per-head split bf16 [bh][s][192]
// SIDE 0 = Q (hi,hi,lo), SIDE 1 = K (hi,lo,hi). One block per m-row.
// ---------------------------------------------------------------------------
template<int SIDE>
__global__ __launch_bounds__(256)
void qk_split(const float* __restrict__ X, __nv_bfloat16* __restrict__ Y)
{
    const int m = blockIdx.x;
    const int b = m >> 11, s = m & (SEQ-1);
    const int t = threadIdx.x;
    const int col = t * 4;
    const int h = col >> 6;
    const int d = col & 63;
    const float4 x = *(const float4*)(X + (size_t)m * DM + col);

    __nv_bfloat16 h0 = __float2bfloat16(x.x), h1 = __float2bfloat16(x.y);
    __nv_bfloat16 h2 = __float2bfloat16(x.z), h3 = __float2bfloat16(x.w);
    __nv_bfloat16 l0 = __float2bfloat16(x.x - __bfloat162float(h0));
    __nv_bfloat16 l1 = __float2bfloat16(x.y - __bfloat162float(h1));
    __nv_bfloat16 l2 = __float2bfloat16(x.z - __bfloat162float(h2));
    __nv_bfloat16 l3 = __float2bfloat16(x.w - __bfloat162float(h3));

    __nv_bfloat162 hA = __halves2bfloat162(h0,h1), hB = __halves2bfloat162(h2,h3);
    __nv_bfloat162 lA = __halves2bfloat162(l0,l1), lB = __halves2bfloat162(l2,l3);

    __nv_bfloat16* base = Y + ((size_t)(b*HEADS + h) * SEQ + s) * 192;
    __nv_bfloat162* y0 = (__nv_bfloat162*)(base + d);
    __nv_bfloat162* y1 = (__nv_bfloat162*)(base + 64 + d);
    __nv_bfloat162* y2 = (__nv_bfloat162*)(base + 128 + d);
    y0[0] = hA; y0[1] = hB;
    if (SIDE == 0) { y1[0] = hA; y1[1] = hB; y2[0] = lA; y2[1] = lB; }
    else           { y1[0] = lA; y1[1] = lB; y2[0] = hA; y2[1] = hB; }
}

// ---------------------------------------------------------------------------
// v_split: fp32 [m][1024] -> bf16 transposed [bh][seg][d=64][s=2048]
// seg0 = hi, seg1 = lo.  One block per (s-block of 128, bh).
// ---------------------------------------------------------------------------
__global__ __launch_bounds__(256)
void v_split(const float* __restrict__ V, __nv_bfloat16* __restrict__ Y)
{
    __shared__ float sm[64][132];
    const int bh = blockIdx.y;
    const int b = bh >> 4, h = bh & 15;
    const int sblk = blockIdx.x * 128;
    const int t = threadIdx.x;

    // read: 128 s-rows x 64 d (coalesced)
    {
        const int srow = t >> 1, half = (t & 1) * 32;
        const float* src = V + ((size_t)b * SEQ + sblk + srow) * DM + h * DKH + half;
        #pragma unroll
        for (int j = 0; j < 8; j++) {
            const float4 v = *(const float4*)(src + j*4);
            sm[half + j*4 + 0][srow] = v.x;
            sm[half + j*4 + 1][srow] = v.y;
            sm[half + j*4 + 2][srow] = v.z;
            sm[half + j*4 + 3][srow] = v.w;
        }
    }
    __syncthreads();
    // write: d-rows, s contiguous
    {
        const int d = t >> 2, sc = (t & 3) * 32;
        __nv_bfloat162* dh = (__nv_bfloat162*)(Y + (((size_t)bh*2 + 0) * DKH + d) * SEQ + sblk + sc);
        __nv_bfloat162* dl = (__nv_bfloat162*)(Y + (((size_t)bh*2 + 1) * DKH + d) * SEQ + sblk + sc);
        #pragma unroll
        for (int j = 0; j < 16; j++) {
            const float a = sm[d][sc + j*2], c = sm[d][sc + j*2 + 1];
            __nv_bfloat16 ha = __float2bfloat16(a), hc = __float2bfloat16(c);
            __nv_bfloat16 la = __float2bfloat16(a - __bfloat162float(ha));
            __nv_bfloat16 lc = __float2bfloat16(c - __bfloat162float(hc));
            dh[j] = __halves2bfloat162(ha, hc);
            dl[j] = __halves2bfloat162(la, lc);
        }
    }
}

// ---------------------------------------------------------------------------
// HMMA flash attention. CTA = 128 q-rows x one (b,h). 8 warps x 16 rows.
// smem: Qs [128][400B], Ks [128][400B], Vs [2][64][272B], Ms [128][272B]
// ---------------------------------------------------------------------------
#define QROWB 400
#define VROWB 272
#define MROWB 272
#define AS_Q  0
#define AS_K  51200
#define AS_V  102400
#define AS_M  137216
#define ASMEM 172032

__global__ __launch_bounds__(256, 1)
void attn_mma(const __nv_bfloat16* __restrict__ Qs, const __nv_bfloat16* __restrict__ Ks,
              const __nv_bfloat16* __restrict__ Vt, const int* __restrict__ mask,
              float* __restrict__ ctx)
{
    extern __shared__ char sm[];
    const uint32_t sb = smem_u32(sm);
    const int tid  = threadIdx.x;
    const int lane = tid & 31;
    const int wm   = (tid >> 5) * 16;
    const int bh   = blockIdx.y;
    const int b    = bh >> 4, h = bh & 15;
    const int q0g  = blockIdx.x * 128;

    const __nv_bfloat16* qb = Qs + ((size_t)bh * SEQ + q0g) * 192;
    const __nv_bfloat16* kb = Ks + (size_t)bh * SEQ * 192;
    const __nv_bfloat16* vb = Vt + (size_t)bh * 2 * DKH * SEQ;
    const int* mb = mask + (size_t)b * SEQ * SEQ + (size_t)q0g * SEQ;

    // staging thread mapping
    const int lrow = tid >> 1, lhalf = tid & 1;

    // load Q tile once (24 chunks/row)
    {
        const uint32_t sq = sb + AS_Q + lrow * QROWB + lhalf * 192;
        const __nv_bfloat16* gq = qb + (size_t)lrow * 192 + lhalf * 96;
        #pragma unroll
        for (int j = 0; j < 12; j++) cpa16(sq + j*16, gq + j*8);
        CPA_COMMIT();
    }

    // fragment smem offsets
    const uint32_t aoffQ = sb + AS_Q + (uint32_t)(wm + (lane & 15)) * QROWB + (lane >> 4) * 16;
    const uint32_t boffK = sb + AS_K + (uint32_t)(((lane >> 4) & 1) * 8 + (lane & 7)) * QROWB
                         + ((lane >> 3) & 1) * 16;
    const uint32_t boffV = sb + AS_V + (uint32_t)(((lane >> 4) & 1) * 8 + (lane & 7)) * VROWB
                         + ((lane >> 3) & 1) * 16;

    const int r0 = lane >> 2;           // warp-local row (and r0+8)
    const int cql = (lane & 3) * 2;     // col within 8-tile

    float o[8][4] = {};
    float m0 = -1e30f, m1 = -1e30f, l0 = 0.f, l1 = 0.f;

    for (int kb0 = 0; kb0 < SEQ; kb0 += 128) {
        __syncthreads();   // previous iteration's smem reads complete
        // stage K tile
        {
            const uint32_t sk = sb + AS_K + lrow * QROWB + lhalf * 192;
            const __nv_bfloat16* gk = kb + ((size_t)(kb0 + lrow)) * 192 + lhalf * 96;
            #pragma unroll
            for (int j = 0; j < 12; j++) cpa16(sk + j*16, gk + j*8);
        }
        // stage V tiles (seg, d-rows)
        {
            const int seg = tid >> 7, vrow = (tid & 127) >> 1;
            const uint32_t sv = sb + AS_V + seg * (64*VROWB) + vrow * VROWB + lhalf * 128;
            const __nv_bfloat16* gv = vb + ((size_t)seg * DKH + vrow) * SEQ + kb0 + lhalf * 64;
            #pragma unroll
            for (int j = 0; j < 8; j++) cpa16(sv + j*16, gv + j*8);
        }
        CPA_COMMIT();
        // stage mask flags as bf16 (1.0 = masked out)
        {
            const int* gm = mb + (size_t)lrow * SEQ + kb0 + lhalf * 64;
            uint32_t smsk = sb + AS_M + lrow * MROWB + lhalf * 128;
            #pragma unroll
            for (int j = 0; j < 16; j++) {
                const int4 mv = *(const int4*)(gm + j*4);
                uint32_t p0 = packbf2(mv.x == 0 ? 1.f : 0.f, mv.y == 0 ? 1.f : 0.f);
                uint32_t p1 = packbf2(mv.z == 0 ? 1.f : 0.f, mv.w == 0 ? 1.f : 0.f);
                uint2 w; w.x = p0; w.y = p1;
                *(uint2*)(sm + (smsk - sb) + j*8) = w;
            }
        }
        CPA_WAIT(0);
        __syncthreads();

        // ---- S = Q K^T (fp32, split K-dim 192) ----
        float s[16][4] = {};
        #pragma unroll
        for (int kk = 0; kk < 12; kk++) {
            uint32_t a0,a1,a2,a3;
            ldsm4(a0,a1,a2,a3, aoffQ + kk*32);
            #pragma unroll
            for (int np = 0; np < 8; np++) {
                uint32_t q0,q1,q2,q3;
                ldsm4(q0,q1,q2,q3, boffK + (uint32_t)np * (16*QROWB) + kk*32);
                mma16816(s[2*np][0], s[2*np][1], s[2*np][2], s[2*np][3], a0,a1,a2,a3, q0,q1);
                mma16816(s[2*np+1][0], s[2*np+1][1], s[2*np+1][2], s[2*np+1][3], a0,a1,a2,a3, q2,q3);
            }
        }

        // ---- mask + scale + row max ----
        float mx0 = -1e30f, mx1 = -1e30f;
        #pragma unroll
        for (int t = 0; t < 16; t++) {
            const uint32_t colb = (uint32_t)(t*8 + cql) * 2;
            uint32_t f0 = *(uint32_t*)(sm + AS_M + (wm + r0) * MROWB + colb);
            uint32_t f1 = *(uint32_t*)(sm + AS_M + (wm + r0 + 8) * MROWB + colb);
            __nv_bfloat162 b0 = *(__nv_bfloat162*)&f0;
            __nv_bfloat162 b1 = *(__nv_bfloat162*)&f1;
            s[t][0] = (__bfloat162float(b0.x) != 0.f) ? -1e9f : s[t][0] * 0.125f;
            s[t][1] = (__bfloat162float(b0.y) != 0.f) ? -1e9f : s[t][1] * 0.125f;
            s[t][2] = (__bfloat162float(b1.x) != 0.f) ? -1e9f : s[t][2] * 0.125f;
            s[t][3] = (__bfloat162float(b1.y) != 0.f) ? -1e9f : s[t][3] * 0.125f;
            mx0 = fmaxf(mx0, fmaxf(s[t][0], s[t][1]));
            mx1 = fmaxf(mx1, fmaxf(s[t][2], s[t][3]));
        }
        mx0 = fmaxf(mx0, __shfl_xor_sync(0xffffffffu, mx0, 1));
        mx0 = fmaxf(mx0, __shfl_xor_sync(0xffffffffu, mx0, 2));
        mx1 = fmaxf(mx1, __shfl_xor_sync(0xffffffffu, mx1, 1));
        mx1 = fmaxf(mx1, __shfl_xor_sync(0xffffffffu, mx1, 2));

        const float nm0 = fmaxf(m0, mx0), nm1 = fmaxf(m1, mx1);
        const float c0 = __expf(m0 - nm0), c1 = __expf(m1 - nm1);
        m0 = nm0; m1 = nm1;

        // ---- exp, row-sum, pack P hi/lo fragments ----
        uint32_t php[16][2], plp[16][2];
        float rs0 = 0.f, rs1 = 0.f;
        #pragma unroll
        for (int t = 0; t < 16; t++) {
            float p0 = __expf(s[t][0] - nm0);
            float p1 = __expf(s[t][1] - nm0);
            float p2 = __expf(s[t][2] - nm1);
            float p3 = __expf(s[t][3] - nm1);
            rs0 += p0 + p1; rs1 += p2 + p3;
            __nv_bfloat16 h0 = __float2bfloat16(p0), h1 = __float2bfloat16(p1);
            __nv_bfloat16 h2 = __float2bfloat16(p2), h3 = __float2bfloat16(p3);
            __nv_bfloat162 ph0 = __halves2bfloat162(h0, h1);
            __nv_bfloat162 ph1 = __halves2bfloat162(h2, h3);
            php[t][0] = *(uint32_t*)&ph0;
            php[t][1] = *(uint32_t*)&ph1;
            __nv_bfloat162 pl0 = __floats2bfloat162_rn(p0 - __bfloat162float(h0),
                                                       p1 - __bfloat162float(h1));
            __nv_bfloat162 pl1 = __floats2bfloat162_rn(p2 - __bfloat162float(h2),
                                                       p3 - __bfloat162float(h3));
            plp[t][0] = *(uint32_t*)&pl0;
            plp[t][1] = *(uint32_t*)&pl1;
        }
        rs0 += __shfl_xor_sync(0xffffffffu, rs0, 1);
        rs0 += __shfl_xor_sync(0xffffffffu, rs0, 2);
        rs1 += __shfl_xor_sync(0xffffffffu, rs1, 1);
        rs1 += __shfl_xor_sync(0xffffffffu, rs1, 2);
        l0 = l0 * c0 + rs0;
        l1 = l1 * c1 + rs1;

        // rescale O
        #pragma unroll
        for (int nt = 0; nt < 8; nt++) {
            o[nt][0] *= c0; o[nt][1] *= c0;
            o[nt][2] *= c1; o[nt][3] *= c1;
        }

        // ---- O += Ph*Vh + Ph*Vl + Pl*Vh ----
        #pragma unroll
        for (int pass = 0; pass < 3; pass++) {
            const uint32_t vseg = (pass == 1) ? (uint32_t)(64*VROWB) : 0u;
            #pragma unroll
            for (int j = 0; j < 8; j++) {
                uint32_t a0, a1, a2, a3;
                if (pass == 2) { a0 = plp[2*j][0]; a1 = plp[2*j][1]; a2 = plp[2*j+1][0]; a3 = plp[2*j+1][1]; }
                else           { a0 = php[2*j][0]; a1 = php[2*j][1]; a2 = php[2*j+1][0]; a3 = php[2*j+1][1]; }
                #pragma unroll
                for (int np = 0; np < 4; np++) {
                    uint32_t q0,q1,q2,q3;
                    ldsm4(q0,q1,q2,q3, boffV + vseg + (uint32_t)np * (16*VROWB) + j*32);
                    mma16816(o[2*np][0], o[2*np][1], o[2*np][2], o[2*np][3], a0,a1,a2,a3, q0,q1);
                    mma16816(o[2*np+1][0], o[2*np+1][1], o[2*np+1][2], o[2*np+1][3], a0,a1,a2,a3, q2,q3);
                }
            }
        }
    }

    // ---- normalize & write ----
    const float i0 = 1.f / l0, i1 = 1.f / l1;
    const int row0 = q0g + wm + r0;
    float* d0 = ctx + ((size_t)b * SEQ + row0) * DM + h * DKH;
    float* d1 = ctx + ((size_t)b * SEQ + row0 + 8) * DM + h * DKH;
    #pragma unroll
    for (int nt = 0; nt < 8; nt++) {
        const int col = nt * 8 + cql;
        float2 w0, w1;
        w0.x = o[nt][0] * i0; w0.y = o[nt][1] * i0;
        w1.x = o[nt][2] * i1; w1.y = o[nt][3] * i1;
        *(float2*)(d0 + col) = w0;
        *(float2*)(d1 + col) = w1;
    }
}

// ---------------------------------------------------------------------------
extern "C" void kernel_launch(void* const* d_in, const int* in_sizes, int n_in,
                              void* d_out, int out_size)
{
    (void)in_sizes; (void)n_in; (void)out_size;
    const float* hid  = (const float*)d_in[0];
    const int*   mask = (const int*)  d_in[1];
    const float* Wq   = (const float*)d_in[2];
    const float* bq   = (const float*)d_in[3];
    const float* Wk   = (const float*)d_in[4];
    const float* bk   = (const float*)d_in[5];
    const float* Wv   = (const float*)d_in[6];
    const float* bv   = (const float*)d_in[7];
    const float* Wo   = (const float*)d_in[8];
    const float* bo   = (const float*)d_in[9];
    float* out = (float*)d_out;

    uint4 *ab, *wb, *cb, *qs, *ks, *vt;
    float *qp, *kp, *vp, *cp;
    cudaGetSymbolAddress((void**)&ab, g_abig);
    cudaGetSymbolAddress((void**)&wb, g_wbig);
    cudaGetSymbolAddress((void**)&cb, g_cbig);
    cudaGetSymbolAddress((void**)&qs, g_qs);
    cudaGetSymbolAddress((void**)&ks, g_ks);
    cudaGetSymbolAddress((void**)&vt, g_vt);
    cudaGetSymbolAddress((void**)&qp, g_q);
    cudaGetSymbolAddress((void**)&kp, g_k);
    cudaGetSymbolAddress((void**)&vp, g_v);
    cudaGetSymbolAddress((void**)&cp, g_ctx);

    const size_t WOFF = (size_t)DM * GK / 8;

    cudaFuncSetAttribute(attn_mma, cudaFuncAttributeMaxDynamicSharedMemorySize, ASMEM);

    split_kernel<0><<<MTOT, 256>>>(hid, (__nv_bfloat16*)ab);
    split_kernel<1><<<DM, 256>>>(Wq, (__nv_bfloat16*)(wb + 0*WOFF));
    split_kernel<1><<<DM, 256>>>(Wk, (__nv_bfloat16*)(wb + 1*WOFF));
    split_kernel<1><<<DM, 256>>>(Wv, (__nv_bfloat16*)(wb + 2*WOFF));
    split_kernel<1><<<DM, 256>>>(Wo, (__nv_bfloat16*)(wb + 3*WOFF));

    const dim3 gg(MTOT/128, DM/128);
    hgemm<<<gg, 256, HSMEM>>>((const __nv_bfloat16*)ab, (const __nv_bfloat16*)(wb + 0*WOFF), bq, qp);
    hgemm<<<gg, 256, HSMEM>>>((const __nv_bfloat16*)ab, (const __nv_bfloat16*)(wb + 1*WOFF), bk, kp);
    hgemm<<<gg, 256, HSMEM>>>((const __nv_bfloat16*)ab, (const __nv_bfloat16*)(wb + 2*WOFF), bv, vp);

    qk_split<0><<<MTOT, 256>>>(qp, (__nv_bfloat16*)qs);
    qk_split<1><<<MTOT, 256>>>(kp, (__nv_bfloat16*)ks);
    v_split<<<dim3(SEQ/128, BATCH*HEADS), 256>>>(vp, (__nv_bfloat16*)vt);

    attn_mma<<<dim3(SEQ/128, BATCH*HEADS), 256, ASMEM>>>(
        (const __nv_bfloat16*)qs, (const __nv_bfloat16*)ks,
        (const __nv_bfloat16*)vt, mask, cp);

    split_kernel<0><<<MTOT, 256>>>(cp, (__nv_bfloat16*)cb);
    hgemm<<<gg, 256, HSMEM>>>((const __nv_bfloat16*)cb, (const __nv_bfloat16*)(wb + 3*WOFF), bo, out);
}

// round 7
// speedup vs baseline: 2.0411x; 1.0337x over previous
#include <cuda_runtime.h>
#include <cuda_bf16.h>
#include <stdint.h>
#include <math.h>

#define DM     1024
#define HEADS  16
#define DKH    64
#define BATCH  2
#define SEQ    2048
#define MTOT   (BATCH*SEQ)
#define GK     3072            // split-bf16 concatenated K (projections)

// ---------------- scratch (static device globals) --------------------------
__device__ uint4 g_abig[(size_t)MTOT * GK * 2 / 16];      // bf16 [4096][3072]
__device__ uint4 g_wbig[(size_t)4 * DM * GK * 2 / 16];    // 4 x bf16 [1024][3072]
__device__ uint4 g_cbig[(size_t)MTOT * GK * 2 / 16];      // bf16 [4096][3072]
__device__ float g_q[(size_t)MTOT * DM];                  // fp32 [m][1024]
__device__ float g_k[(size_t)MTOT * DM];
__device__ float g_v[(size_t)MTOT * DM];
__device__ float g_ctx[(size_t)MTOT * DM];
// attention operands
__device__ uint4 g_qs[(size_t)32 * SEQ * 192 * 2 / 16];   // bf16 [bh][s][192] (hi,hi,lo)
__device__ uint4 g_ks[(size_t)32 * SEQ * 192 * 2 / 16];   // bf16 [bh][s][192] (hi,lo,hi)
__device__ uint4 g_vt[(size_t)32 * 2 * DKH * SEQ * 2 / 16]; // bf16 [bh][seg][d][s]
__device__ uint32_t g_mbits[(size_t)BATCH * SEQ * SEQ / 32]; // packed mask bits

// ---------------- small helpers --------------------------------------------
__device__ __forceinline__ uint32_t smem_u32(const void* p) {
    uint32_t a;
    asm("{ .reg .u64 t; cvta.to.shared.u64 t, %1; cvt.u32.u64 %0, t; }" : "=r"(a) : "l"(p));
    return a;
}
__device__ __forceinline__ void cpa16(uint32_t s, const void* g) {
    asm volatile("cp.async.cg.shared.global [%0], [%1], 16;" :: "r"(s), "l"(g));
}
#define CPA_COMMIT() asm volatile("cp.async.commit_group;" ::: "memory")
#define CPA_WAIT(N)  asm volatile("cp.async.wait_group %0;" :: "n"(N) : "memory")

__device__ __forceinline__ void ldsm4(uint32_t& r0, uint32_t& r1, uint32_t& r2, uint32_t& r3,
                                      uint32_t addr) {
    asm volatile("ldmatrix.sync.aligned.m8n8.x4.shared.b16 {%0,%1,%2,%3}, [%4];"
                 : "=r"(r0), "=r"(r1), "=r"(r2), "=r"(r3) : "r"(addr));
}
__device__ __forceinline__ void mma16816(float& d0, float& d1, float& d2, float& d3,
                                         uint32_t a0, uint32_t a1, uint32_t a2, uint32_t a3,
                                         uint32_t b0, uint32_t b1) {
    asm volatile("mma.sync.aligned.m16n8k16.row.col.f32.bf16.bf16.f32 "
                 "{%0,%1,%2,%3}, {%4,%5,%6,%7}, {%8,%9}, {%0,%1,%2,%3};"
                 : "+f"(d0), "+f"(d1), "+f"(d2), "+f"(d3)
                 : "r"(a0), "r"(a1), "r"(a2), "r"(a3), "r"(b0), "r"(b1));
}

// ---------------------------------------------------------------------------
// mask_pack: int32 mask [b][sq][sk] -> bit per element (1 = keep)
// ---------------------------------------------------------------------------
__global__ __launch_bounds__(256)
void mask_pack(const int* __restrict__ mask, uint32_t* __restrict__ bits)
{
    const size_t tid = (size_t)blockIdx.x * 256 + threadIdx.x;
    const int lane = threadIdx.x & 31;
    const int mv = mask[tid];
    const uint32_t w = __ballot_sync(0xffffffffu, mv != 0);
    if (lane == 0) bits[tid >> 5] = w;
}

// ---------------------------------------------------------------------------
// split: X fp32 [rows][1024] -> Y bf16 [rows][3072]
// SIDE 0 (A operand): (hi,hi,lo);  SIDE 1 (B): (hi,lo,hi)
// ---------------------------------------------------------------------------
template<int SIDE>
__global__ __launch_bounds__(256)
void split_kernel(const float* __restrict__ X, __nv_bfloat16* __restrict__ Y)
{
    const int idx = blockIdx.x * 256 + threadIdx.x;
    const int r   = idx >> 8;
    const int c4  = (idx & 255) * 4;
    const float4 x = *(const float4*)(X + (size_t)r * DM + c4);

    __nv_bfloat16 h0 = __float2bfloat16(x.x), h1 = __float2bfloat16(x.y);
    __nv_bfloat16 h2 = __float2bfloat16(x.z), h3 = __float2bfloat16(x.w);
    __nv_bfloat16 l0 = __float2bfloat16(x.x - __bfloat162float(h0));
    __nv_bfloat16 l1 = __float2bfloat16(x.y - __bfloat162float(h1));
    __nv_bfloat16 l2 = __float2bfloat16(x.z - __bfloat162float(h2));
    __nv_bfloat16 l3 = __float2bfloat16(x.w - __bfloat162float(h3));

    __nv_bfloat162 hA = __halves2bfloat162(h0,h1), hB = __halves2bfloat162(h2,h3);
    __nv_bfloat162 lA = __halves2bfloat162(l0,l1), lB = __halves2bfloat162(l2,l3);

    __nv_bfloat162* y0 = (__nv_bfloat162*)(Y + (size_t)r * GK + c4);
    __nv_bfloat162* y1 = (__nv_bfloat162*)(Y + (size_t)r * GK + 1024 + c4);
    __nv_bfloat162* y2 = (__nv_bfloat162*)(Y + (size_t)r * GK + 2048 + c4);
    y0[0] = hA; y0[1] = hB;
    if (SIDE == 0) { y1[0] = hA; y1[1] = hB; y2[0] = lA; y2[1] = lB; }
    else           { y1[0] = lA; y1[1] = lB; y2[0] = hA; y2[1] = hB; }
}

// ---------------------------------------------------------------------------
// HMMA GEMM (unchanged — known good)
// ---------------------------------------------------------------------------
#define ROWB   80
#define TILEB  (128*ROWB)
#define HS_A0  0
#define HS_B0  TILEB
#define HS_A1  (2*TILEB)
#define HS_B1  (3*TILEB)
#define HSMEM  (4*TILEB)

__global__ __launch_bounds__(256, 2)
void hgemm(const __nv_bfloat16* __restrict__ A, const __nv_bfloat16* __restrict__ B,
           const float* __restrict__ bias, float* __restrict__ out)
{
    extern __shared__ char sm[];
    const uint32_t sbase = smem_u32(sm);
    const int tid  = threadIdx.x;
    const int m0   = blockIdx.x * 128;
    const int n0   = blockIdx.y * 128;

    const int r0c = tid >> 2,  c0c = tid & 3;
    const int r1c = r0c + 64;
    const __nv_bfloat16* Ag0 = A + (size_t)(m0 + r0c) * GK + c0c * 8;
    const __nv_bfloat16* Ag1 = A + (size_t)(m0 + r1c) * GK + c0c * 8;
    const __nv_bfloat16* Bg0 = B + (size_t)(n0 + r0c) * GK + c0c * 8;
    const __nv_bfloat16* Bg1 = B + (size_t)(n0 + r1c) * GK + c0c * 8;
    const uint32_t sA_off0 = r0c * ROWB + c0c * 16;
    const uint32_t sA_off1 = r1c * ROWB + c0c * 16;

    const uint32_t abuf[2] = { sbase + HS_A0, sbase + HS_A1 };
    const uint32_t bbuf[2] = { sbase + HS_B0, sbase + HS_B1 };

    const int wid  = tid >> 5, lane = tid & 31;
    const int wm   = (wid >> 2) * 64;
    const int wn   = (wid & 3) * 32;

    const uint32_t aoff = (uint32_t)(wm + (lane & 15)) * ROWB + (lane >> 4) * 16;
    const uint32_t boff = (uint32_t)(wn + ((lane >> 4) & 1) * 8 + (lane & 7)) * ROWB
                        + ((lane >> 3) & 1) * 16;

    float acc[4][4][4] = {};

    #define LOAD_TILE(it, buf) do {                                            \
        const size_t kb = (size_t)(it) * 32;                                   \
        cpa16(abuf[buf] + sA_off0, Ag0 + kb);                                  \
        cpa16(abuf[buf] + sA_off1, Ag1 + kb);                                  \
        cpa16(bbuf[buf] + sA_off0, Bg0 + kb);                                  \
        cpa16(bbuf[buf] + sA_off1, Bg1 + kb);                                  \
        CPA_COMMIT();                                                          \
    } while (0)

    LOAD_TILE(0, 0);

    const int KITERS = GK / 32;
    for (int it = 0; it < KITERS; it++) {
        const int cur = it & 1;
        if (it + 1 < KITERS) { LOAD_TILE(it + 1, cur ^ 1); CPA_WAIT(1); }
        else                 { CPA_WAIT(0); }
        __syncthreads();

        #pragma unroll
        for (int kk = 0; kk < 2; kk++) {
            const uint32_t kb = kk * 32;
            uint32_t a[4][4], b[4][2];
            #pragma unroll
            for (int mt = 0; mt < 4; mt++)
                ldsm4(a[mt][0], a[mt][1], a[mt][2], a[mt][3],
                      abuf[cur] + aoff + (uint32_t)mt * (16*ROWB) + kb);
            #pragma unroll
            for (int np = 0; np < 2; np++) {
                uint32_t q0,q1,q2,q3;
                ldsm4(q0,q1,q2,q3, bbuf[cur] + boff + (uint32_t)np * (16*ROWB) + kb);
                b[np*2+0][0] = q0; b[np*2+0][1] = q1;
                b[np*2+1][0] = q2; b[np*2+1][1] = q3;
            }
            #pragma unroll
            for (int mt = 0; mt < 4; mt++)
                #pragma unroll
                for (int nt = 0; nt < 4; nt++)
                    mma16816(acc[mt][nt][0], acc[mt][nt][1], acc[mt][nt][2], acc[mt][nt][3],
                             a[mt][0], a[mt][1], a[mt][2], a[mt][3],
                             b[nt][0], b[nt][1]);
        }
        __syncthreads();
    }

    const int erow = lane >> 2;
    const int ecol = (lane & 3) * 2;
    #pragma unroll
    for (int nt = 0; nt < 4; nt++) {
        const int col = n0 + wn + nt * 8 + ecol;
        const float2 bv = *(const float2*)(bias + col);
        #pragma unroll
        for (int mt = 0; mt < 4; mt++) {
            const int m = m0 + wm + mt * 16 + erow;
            float2 w0, w1;
            w0.x = acc[mt][nt][0] + bv.x; w0.y = acc[mt][nt][1] + bv.y;
            w1.x = acc[mt][nt][2] + bv.x; w1.y = acc[mt][nt][3] + bv.y;
            *(float2*)(out + (size_t)m * DM + col)       = w0;
            *(float2*)(out + (size_t)(m + 8) * DM + col) = w1;
        }
    }
    #undef LOAD_TILE
}

// ---------------------------------------------------------------------------
// qk_split: fp32 [m][1024] -> per-head split bf16 [bh][s][192]
// SIDE 0 = Q (hi,hi,lo), SIDE 1 = K (hi,lo,hi)
// ---------------------------------------------------------------------------
template<int SIDE>
__global__ __launch_bounds__(256)
void qk_split(const float* __restrict__ X, __nv_bfloat16* __restrict__ Y)
{
    const int m = blockIdx.x;
    const int b = m >> 11, s = m & (SEQ-1);
    const int t = threadIdx.x;
    const int col = t * 4;
    const int h = col >> 6;
    const int d = col & 63;
    const float4 x = *(const float4*)(X + (size_t)m * DM + col);

    __nv_bfloat16 h0 = __float2bfloat16(x.x), h1 = __float2bfloat16(x.y);
    __nv_bfloat16 h2 = __float2bfloat16(x.z), h3 = __float2bfloat16(x.w);
    __nv_bfloat16 l0 = __float2bfloat16(x.x - __bfloat162float(h0));
    __nv_bfloat16 l1 = __float2bfloat16(x.y - __bfloat162float(h1));
    __nv_bfloat16 l2 = __float2bfloat16(x.z - __bfloat162float(h2));
    __nv_bfloat16 l3 = __float2bfloat16(x.w - __bfloat162float(h3));

    __nv_bfloat162 hA = __halves2bfloat162(h0,h1), hB = __halves2bfloat162(h2,h3);
    __nv_bfloat162 lA = __halves2bfloat162(l0,l1), lB = __halves2bfloat162(l2,l3);

    __nv_bfloat16* base = Y + ((size_t)(b*HEADS + h) * SEQ + s) * 192;
    __nv_bfloat162* y0 = (__nv_bfloat162*)(base + d);
    __nv_bfloat162* y1 = (__nv_bfloat162*)(base + 64 + d);
    __nv_bfloat162* y2 = (__nv_bfloat162*)(base + 128 + d);
    y0[0] = hA; y0[1] = hB;
    if (SIDE == 0) { y1[0] = hA; y1[1] = hB; y2[0] = lA; y2[1] = lB; }
    else           { y1[0] = lA; y1[1] = lB; y2[0] = hA; y2[1] = hB; }
}

// ---------------------------------------------------------------------------
// v_split: fp32 [m][1024] -> bf16 transposed [bh][seg][d=64][s=2048]
// ---------------------------------------------------------------------------
__global__ __launch_bounds__(256)
void v_split(const float* __restrict__ V, __nv_bfloat16* __restrict__ Y)
{
    __shared__ float sm[64][132];
    const int bh = blockIdx.y;
    const int b = bh >> 4, h = bh & 15;
    const int sblk = blockIdx.x * 128;
    const int t = threadIdx.x;

    {
        const int srow = t >> 1, half = (t & 1) * 32;
        const float* src = V + ((size_t)b * SEQ + sblk + srow) * DM + h * DKH + half;
        #pragma unroll
        for (int j = 0; j < 8; j++) {
            const float4 v = *(const float4*)(src + j*4);
            sm[half + j*4 + 0][srow] = v.x;
            sm[half + j*4 + 1][srow] = v.y;
            sm[half + j*4 + 2][srow] = v.z;
            sm[half + j*4 + 3][srow] = v.w;
        }
    }
    __syncthreads();
    {
        const int d = t >> 2, sc = (t & 3) * 32;
        __nv_bfloat162* dh = (__nv_bfloat162*)(Y + (((size_t)bh*2 + 0) * DKH + d) * SEQ + sblk + sc);
        __nv_bfloat162* dl = (__nv_bfloat162*)(Y + (((size_t)bh*2 + 1) * DKH + d) * SEQ + sblk + sc);
        #pragma unroll
        for (int j = 0; j < 16; j++) {
            const float a = sm[d][sc + j*2], c = sm[d][sc + j*2 + 1];
            __nv_bfloat16 ha = __float2bfloat16(a), hc = __float2bfloat16(c);
            __nv_bfloat16 la = __float2bfloat16(a - __bfloat162float(ha));
            __nv_bfloat16 lc = __float2bfloat16(c - __bfloat162float(hc));
            dh[j] = __halves2bfloat162(ha, hc);
            dl[j] = __halves2bfloat162(la, lc);
        }
    }
}

// ---------------------------------------------------------------------------
// HMMA flash attention, double-buffered K/V, bit-packed mask.
// smem: Qs [128][400B] | K0,K1 [128][400B] | V0,V1 [2][64][272B]
// ---------------------------------------------------------------------------
#define QROWB 400
#define VROWB 272
#define AS_Q  0
#define AS_K0 51200
#define AS_K1 102400
#define AS_V0 153600
#define AS_V1 188416
#define ASMEM 223232

__global__ __launch_bounds__(256, 1)
void attn_mma(const __nv_bfloat16* __restrict__ Qs, const __nv_bfloat16* __restrict__ Ks,
              const __nv_bfloat16* __restrict__ Vt, const uint32_t* __restrict__ mbits,
              float* __restrict__ ctx)
{
    extern __shared__ char sm[];
    const uint32_t sb = smem_u32(sm);
    const int tid  = threadIdx.x;
    const int lane = tid & 31;
    const int wm   = (tid >> 5) * 16;
    const int bh   = blockIdx.y;
    const int b    = bh >> 4, h = bh & 15;
    const int q0g  = blockIdx.x * 128;

    const __nv_bfloat16* qb = Qs + ((size_t)bh * SEQ + q0g) * 192;
    const __nv_bfloat16* kb = Ks + (size_t)bh * SEQ * 192;
    const __nv_bfloat16* vb = Vt + (size_t)bh * 2 * DKH * SEQ;

    const int lrow = tid >> 1, lhalf = tid & 1;

    // Q tile once
    {
        const uint32_t sq = sb + AS_Q + lrow * QROWB + lhalf * 192;
        const __nv_bfloat16* gq = qb + (size_t)lrow * 192 + lhalf * 96;
        #pragma unroll
        for (int j = 0; j < 12; j++) cpa16(sq + j*16, gq + j*8);
        CPA_COMMIT();
    }

    const uint32_t kbuf[2] = { sb + AS_K0, sb + AS_K1 };
    const uint32_t vbuf[2] = { sb + AS_V0, sb + AS_V1 };

    const uint32_t aoffQ = sb + AS_Q + (uint32_t)(wm + (lane & 15)) * QROWB + (lane >> 4) * 16;
    const uint32_t boffK = (uint32_t)(((lane >> 4) & 1) * 8 + (lane & 7)) * QROWB
                         + ((lane >> 3) & 1) * 16;
    const uint32_t boffV = (uint32_t)(((lane >> 4) & 1) * 8 + (lane & 7)) * VROWB
                         + ((lane >> 3) & 1) * 16;

    const int r0 = lane >> 2;
    const int cql = (lane & 3) * 2;

    // packed-mask row pointers (words of 32 bits; row stride SEQ/32 = 64)
    const uint32_t* mrow0 = mbits + ((size_t)b * SEQ + (q0g + wm + r0)) * (SEQ/32);
    const uint32_t* mrow1 = mrow0 + 8 * (SEQ/32);

    #define STAGE_KV(it, buf) do {                                                     \
        const int kb0_ = (it) * 128;                                                   \
        const uint32_t sk = kbuf[buf] + lrow * QROWB + lhalf * 192;                    \
        const __nv_bfloat16* gk = kb + ((size_t)(kb0_ + lrow)) * 192 + lhalf * 96;     \
        _Pragma("unroll")                                                              \
        for (int j = 0; j < 12; j++) cpa16(sk + j*16, gk + j*8);                       \
        const int seg_ = tid >> 7, vrow_ = (tid & 127) >> 1;                           \
        const uint32_t sv = vbuf[buf] + seg_ * (64*VROWB) + vrow_ * VROWB + lhalf*128; \
        const __nv_bfloat16* gv = vb + ((size_t)seg_ * DKH + vrow_) * SEQ + kb0_ + lhalf*64; \
        _Pragma("unroll")                                                              \
        for (int j = 0; j < 8; j++) cpa16(sv + j*16, gv + j*8);                        \
        CPA_COMMIT();                                                                  \
    } while (0)

    STAGE_KV(0, 0);

    float o[8][4] = {};
    float m0 = -1e30f, m1 = -1e30f, l0 = 0.f, l1 = 0.f;

    for (int it = 0; it < SEQ/128; it++) {
        const int cur = it & 1;
        const int kb0 = it * 128;
        if (it + 1 < SEQ/128) { STAGE_KV(it + 1, cur ^ 1); CPA_WAIT(1); }
        else                  { CPA_WAIT(0); }
        __syncthreads();

        // ---- S = Q K^T ----
        float s[16][4] = {};
        #pragma unroll
        for (int kk = 0; kk < 12; kk++) {
            uint32_t a0,a1,a2,a3;
            ldsm4(a0,a1,a2,a3, aoffQ + kk*32);
            #pragma unroll
            for (int np = 0; np < 8; np++) {
                uint32_t q0,q1,q2,q3;
                ldsm4(q0,q1,q2,q3, kbuf[cur] + boffK + (uint32_t)np * (16*QROWB) + kk*32);
                mma16816(s[2*np][0], s[2*np][1], s[2*np][2], s[2*np][3], a0,a1,a2,a3, q0,q1);
                mma16816(s[2*np+1][0], s[2*np+1][1], s[2*np+1][2], s[2*np+1][3], a0,a1,a2,a3, q2,q3);
            }
        }

        // ---- mask (bits) + scale + row max ----
        const uint4 mq0 = *(const uint4*)(mrow0 + (kb0 >> 5));
        const uint4 mq1 = *(const uint4*)(mrow1 + (kb0 >> 5));
        const uint32_t w0[4] = { mq0.x, mq0.y, mq0.z, mq0.w };
        const uint32_t w1[4] = { mq1.x, mq1.y, mq1.z, mq1.w };
        float mx0 = -1e30f, mx1 = -1e30f;
        #pragma unroll
        for (int t = 0; t < 16; t++) {
            const int sh = (t & 3) * 8 + cql;
            const uint32_t a = w0[t >> 2] >> sh;
            const uint32_t c = w1[t >> 2] >> sh;
            s[t][0] = (a & 1u) ? s[t][0] * 0.125f : -1e9f;
            s[t][1] = (a & 2u) ? s[t][1] * 0.125f : -1e9f;
            s[t][2] = (c & 1u) ? s[t][2] * 0.125f : -1e9f;
            s[t][3] = (c & 2u) ? s[t][3] * 0.125f : -1e9f;
            mx0 = fmaxf(mx0, fmaxf(s[t][0], s[t][1]));
            mx1 = fmaxf(mx1, fmaxf(s[t][2], s[t][3]));
        }
        mx0 = fmaxf(mx0, __shfl_xor_sync(0xffffffffu, mx0, 1));
        mx0 = fmaxf(mx0, __shfl_xor_sync(0xffffffffu, mx0, 2));
        mx1 = fmaxf(mx1, __shfl_xor_sync(0xffffffffu, mx1, 1));
        mx1 = fmaxf(mx1, __shfl_xor_sync(0xffffffffu, mx1, 2));

        const float nm0 = fmaxf(m0, mx0), nm1 = fmaxf(m1, mx1);
        const float c0 = __expf(m0 - nm0), c1 = __expf(m1 - nm1);
        m0 = nm0; m1 = nm1;

        // ---- exp, row-sum, pack P hi/lo fragments ----
        uint32_t php[16][2], plp[16][2];
        float rs0 = 0.f, rs1 = 0.f;
        #pragma unroll
        for (int t = 0; t < 16; t++) {
            float p0 = __expf(s[t][0] - nm0);
            float p1 = __expf(s[t][1] - nm0);
            float p2 = __expf(s[t][2] - nm1);
            float p3 = __expf(s[t][3] - nm1);
            rs0 += p0 + p1; rs1 += p2 + p3;
            __nv_bfloat16 h0 = __float2bfloat16(p0), h1 = __float2bfloat16(p1);
            __nv_bfloat16 h2 = __float2bfloat16(p2), h3 = __float2bfloat16(p3);
            __nv_bfloat162 ph0 = __halves2bfloat162(h0, h1);
            __nv_bfloat162 ph1 = __halves2bfloat162(h2, h3);
            php[t][0] = *(uint32_t*)&ph0;
            php[t][1] = *(uint32_t*)&ph1;
            __nv_bfloat162 pl0 = __floats2bfloat162_rn(p0 - __bfloat162float(h0),
                                                       p1 - __bfloat162float(h1));
            __nv_bfloat162 pl1 = __floats2bfloat162_rn(p2 - __bfloat162float(h2),
                                                       p3 - __bfloat162float(h3));
            plp[t][0] = *(uint32_t*)&pl0;
            plp[t][1] = *(uint32_t*)&pl1;
        }
        rs0 += __shfl_xor_sync(0xffffffffu, rs0, 1);
        rs0 += __shfl_xor_sync(0xffffffffu, rs0, 2);
        rs1 += __shfl_xor_sync(0xffffffffu, rs1, 1);
        rs1 += __shfl_xor_sync(0xffffffffu, rs1, 2);
        l0 = l0 * c0 + rs0;
        l1 = l1 * c1 + rs1;

        #pragma unroll
        for (int nt = 0; nt < 8; nt++) {
            o[nt][0] *= c0; o[nt][1] *= c0;
            o[nt][2] *= c1; o[nt][3] *= c1;
        }

        // ---- O += Ph*Vh + Ph*Vl + Pl*Vh ----
        #pragma unroll
        for (int pass = 0; pass < 3; pass++) {
            const uint32_t vseg = (pass == 1) ? (uint32_t)(64*VROWB) : 0u;
            #pragma unroll
            for (int j = 0; j < 8; j++) {
                uint32_t a0, a1, a2, a3;
                if (pass == 2) { a0 = plp[2*j][0]; a1 = plp[2*j][1]; a2 = plp[2*j+1][0]; a3 = plp[2*j+1][1]; }
                else           { a0 = php[2*j][0]; a1 = php[2*j][1]; a2 = php[2*j+1][0]; a3 = php[2*j+1][1]; }
                #pragma unroll
                for (int np = 0; np < 4; np++) {
                    uint32_t q0,q1,q2,q3;
                    ldsm4(q0,q1,q2,q3, vbuf[cur] + boffV + vseg + (uint32_t)np * (16*VROWB) + j*32);
                    mma16816(o[2*np][0], o[2*np][1], o[2*np][2], o[2*np][3], a0,a1,a2,a3, q0,q1);
                    mma16816(o[2*np+1][0], o[2*np+1][1], o[2*np+1][2], o[2*np+1][3], a0,a1,a2,a3, q2,q3);
                }
            }
        }
        __syncthreads();   // all reads of buffer `cur` done before it is restaged
    }

    // ---- normalize & write ----
    const float i0 = 1.f / l0, i1 = 1.f / l1;
    const int row0 = q0g + wm + r0;
    float* d0 = ctx + ((size_t)b * SEQ + row0) * DM + h * DKH;
    float* d1 = ctx + ((size_t)b * SEQ + row0 + 8) * DM + h * DKH;
    #pragma unroll
    for (int nt = 0; nt < 8; nt++) {
        const int col = nt * 8 + cql;
        float2 v0, v1;
        v0.x = o[nt][0] * i0; v0.y = o[nt][1] * i0;
        v1.x = o[nt][2] * i1; v1.y = o[nt][3] * i1;
        *(float2*)(d0 + col) = v0;
        *(float2*)(d1 + col) = v1;
    }
    #undef STAGE_KV
}

// ---------------------------------------------------------------------------
extern "C" void kernel_launch(void* const* d_in, const int* in_sizes, int n_in,
                              void* d_out, int out_size)
{
    (void)in_sizes; (void)n_in; (void)out_size;
    const float* hid  = (const float*)d_in[0];
    const int*   mask = (const int*)  d_in[1];
    const float* Wq   = (const float*)d_in[2];
    const float* bq   = (const float*)d_in[3];
    const float* Wk   = (const float*)d_in[4];
    const float* bk   = (const float*)d_in[5];
    const float* Wv   = (const float*)d_in[6];
    const float* bv   = (const float*)d_in[7];
    const float* Wo   = (const float*)d_in[8];
    const float* bo   = (const float*)d_in[9];
    float* out = (float*)d_out;

    uint4 *ab, *wb, *cb, *qs, *ks, *vt;
    float *qp, *kp, *vp, *cp;
    uint32_t* mbp;
    cudaGetSymbolAddress((void**)&ab, g_abig);
    cudaGetSymbolAddress((void**)&wb, g_wbig);
    cudaGetSymbolAddress((void**)&cb, g_cbig);
    cudaGetSymbolAddress((void**)&qs, g_qs);
    cudaGetSymbolAddress((void**)&ks, g_ks);
    cudaGetSymbolAddress((void**)&vt, g_vt);
    cudaGetSymbolAddress((void**)&qp, g_q);
    cudaGetSymbolAddress((void**)&kp, g_k);
    cudaGetSymbolAddress((void**)&vp, g_v);
    cudaGetSymbolAddress((void**)&cp, g_ctx);
    cudaGetSymbolAddress((void**)&mbp, g_mbits);

    const size_t WOFF = (size_t)DM * GK / 8;

    cudaFuncSetAttribute(attn_mma, cudaFuncAttributeMaxDynamicSharedMemorySize, ASMEM);

    mask_pack<<<(size_t)BATCH*SEQ*SEQ/256, 256>>>(mask, mbp);

    split_kernel<0><<<MTOT, 256>>>(hid, (__nv_bfloat16*)ab);
    split_kernel<1><<<DM, 256>>>(Wq, (__nv_bfloat16*)(wb + 0*WOFF));
    split_kernel<1><<<DM, 256>>>(Wk, (__nv_bfloat16*)(wb + 1*WOFF));
    split_kernel<1><<<DM, 256>>>(Wv, (__nv_bfloat16*)(wb + 2*WOFF));
    split_kernel<1><<<DM, 256>>>(Wo, (__nv_bfloat16*)(wb + 3*WOFF));

    const dim3 gg(MTOT/128, DM/128);
    hgemm<<<gg, 256, HSMEM>>>((const __nv_bfloat16*)ab, (const __nv_bfloat16*)(wb + 0*WOFF), bq, qp);
    hgemm<<<gg, 256, HSMEM>>>((const __nv_bfloat16*)ab, (const __nv_bfloat16*)(wb + 1*WOFF), bk, kp);
    hgemm<<<gg, 256, HSMEM>>>((const __nv_bfloat16*)ab, (const __nv_bfloat16*)(wb + 2*WOFF), bv, vp);

    qk_split<0><<<MTOT, 256>>>(qp, (__nv_bfloat16*)qs);
    qk_split<1><<<MTOT, 256>>>(kp, (__nv_bfloat16*)ks);
    v_split<<<dim3(SEQ/128, BATCH*HEADS), 256>>>(vp, (__nv_bfloat16*)vt);

    attn_mma<<<dim3(SEQ/128, BATCH*HEADS), 256, ASMEM>>>(
        (const __nv_bfloat16*)qs, (const __nv_bfloat16*)ks,
        (const __nv_bfloat16*)vt, mbp, cp);

    split_kernel<0><<<MTOT, 256>>>(cp, (__nv_bfloat16*)cb);
    hgemm<<<gg, 256, HSMEM>>>((const __nv_bfloat16*)cb, (const __nv_bfloat16*)(wb + 3*WOFF), bo, out);
}